// round 2
// baseline (speedup 1.0000x reference)
#include <cuda_runtime.h>

#define SEQ   1024
#define BATCH 512
#define NT    64

// Per-batch partials (device scratch; no allocations allowed)
__device__ float g_num[BATCH];
__device__ float g_den[BATCH];
__device__ int   g_tags_is64;

// ---------------------------------------------------------------------------
// Detect tags dtype: int64 (odd int32 words all zero for values in [0,64))
// vs int32. Misclassification probability ~ (1/64)^64 ~= 0.
// ---------------------------------------------------------------------------
__global__ void detect_kernel(const int* __restrict__ tags32)
{
    int all_hi_zero = 1;
    #pragma unroll
    for (int k = 0; k < 64; k++) {
        if (tags32[2 * k + 1] != 0) { all_hi_zero = 0; break; }
    }
    g_tags_is64 = all_hi_zero;
}

// ---------------------------------------------------------------------------
// Numerator: per-batch gold-path score
// ---------------------------------------------------------------------------
__global__ __launch_bounds__(64) void numer_kernel(
    const float* __restrict__ em,
    const void* __restrict__ tags_raw,
    const int* __restrict__ mask,
    const float* __restrict__ startT,
    const float* __restrict__ endT,
    const float* __restrict__ trans)
{
    int b   = blockIdx.x;
    int tid = threadIdx.x;  // 0..63

    const int is64 = g_tags_is64;
    const long long* tags64 = (const long long*)tags_raw;
    const int*       tags32 = (const int*)tags_raw;

    __shared__ int stags[SEQ];
    __shared__ int smask[SEQ];
    for (int t = tid; t < SEQ; t += 64) {
        size_t idx = (size_t)t * BATCH + b;
        stags[t] = is64 ? (int)tags64[idx] : tags32[idx];
        smask[t] = mask[t * BATCH + b];
    }
    __syncthreads();

    float score  = 0.f;
    int   mcount = 0;
    for (int t = tid; t < SEQ; t += 64) {
        int tg = stags[t];
        mcount += smask[t];
        if (t == 0) {
            score += startT[tg] + em[(size_t)b * NT + tg];
        } else if (smask[t]) {
            score += trans[stags[t - 1] * NT + tg] +
                     em[((size_t)t * BATCH + b) * NT + tg];
        }
    }

    // reduce over 64 threads
    #pragma unroll
    for (int o = 16; o; o >>= 1) {
        score  += __shfl_down_sync(0xffffffffu, score, o);
        mcount += __shfl_down_sync(0xffffffffu, mcount, o);
    }
    __shared__ float ws[2];
    __shared__ int   wm[2];
    if ((tid & 31) == 0) { ws[tid >> 5] = score; wm[tid >> 5] = mcount; }
    __syncthreads();
    if (tid == 0) {
        float s  = ws[0] + ws[1];
        int   mc = wm[0] + wm[1];
        int last = mc - 1;
        s += endT[stags[last]];
        g_num[b] = s;
    }
}

// ---------------------------------------------------------------------------
// Normalizer: scaled forward algorithm in exp domain.
// One block per batch, 64 threads (thread j owns tag column j).
// E[:,j] = exp(T[:,j]) held in registers. a[] (normalized exp(alpha)) in smem.
// ---------------------------------------------------------------------------
__global__ __launch_bounds__(64) void forward_kernel(
    const float* __restrict__ em,
    const int* __restrict__ mask,
    const float* __restrict__ startT,
    const float* __restrict__ endT,
    const float* __restrict__ trans)
{
    int b = blockIdx.x;
    int j = threadIdx.x;  // 0..63

    float Ecol[NT];
    #pragma unroll
    for (int i = 0; i < NT; i++)
        Ecol[i] = __expf(trans[i * NT + j]);

    __shared__ float a_s[2][NT];
    __shared__ float wred[2];

    // t = 0: alpha0 = start + em0  (exp domain, logacc = 0)
    float a0 = __expf(startT[j] + em[(size_t)b * NT + j]);
    a_s[0][j] = a0;
    __syncthreads();

    float logacc = 0.f;
    int   p      = 0;

    // prefetch t=1
    float em_next = em[((size_t)1 * BATCH + b) * NT + j];
    int   m_next  = mask[1 * BATCH + b];

    for (int t = 1; t < SEQ; t++) {
        float emc = em_next;
        int   mc  = m_next;
        if (t + 1 < SEQ) {
            em_next = em[((size_t)(t + 1) * BATCH + b) * NT + j];
            m_next  = mask[(t + 1) * BATCH + b];
        }

        float v;
        if (mc) {
            float acc0 = 0.f, acc1 = 0.f, acc2 = 0.f, acc3 = 0.f;
            #pragma unroll
            for (int i = 0; i < NT; i += 4) {
                float4 av = *(const float4*)&a_s[p][i];  // broadcast load
                acc0 = fmaf(av.x, Ecol[i + 0], acc0);
                acc1 = fmaf(av.y, Ecol[i + 1], acc1);
                acc2 = fmaf(av.z, Ecol[i + 2], acc2);
                acc3 = fmaf(av.w, Ecol[i + 3], acc3);
            }
            v = ((acc0 + acc1) + (acc2 + acc3)) * __expf(emc);
        } else {
            v = a_s[p][j];  // masked step: alpha unchanged
        }

        // renormalize every 8 steps (growth/step <~1e3, fp32-safe for 8)
        if ((t & 7) == 0) {
            float s = v;
            #pragma unroll
            for (int o = 16; o; o >>= 1)
                s += __shfl_xor_sync(0xffffffffu, s, o);
            if ((j & 31) == 0) wred[j >> 5] = s;
            __syncthreads();
            s = wred[0] + wred[1];
            v *= (1.0f / s);
            logacc += __logf(s);
        }

        a_s[p ^ 1][j] = v;
        __syncthreads();
        p ^= 1;
    }

    // logZ = logacc + log( sum_j a_j * exp(end_j) )
    float ve = a_s[p][j] * __expf(endT[j]);
    float s  = ve;
    #pragma unroll
    for (int o = 16; o; o >>= 1)
        s += __shfl_xor_sync(0xffffffffu, s, o);
    if ((j & 31) == 0) wred[j >> 5] = s;
    __syncthreads();
    if (j == 0)
        g_den[b] = logacc + __logf(wred[0] + wred[1]);
}

// ---------------------------------------------------------------------------
// Deterministic final reduction: out = sum_b (num[b] - den[b])
// ---------------------------------------------------------------------------
__global__ void reduce_kernel(float* __restrict__ out)
{
    __shared__ float s[BATCH];
    int tid = threadIdx.x;
    s[tid] = g_num[tid] - g_den[tid];
    __syncthreads();
    #pragma unroll
    for (int stride = BATCH / 2; stride > 0; stride >>= 1) {
        if (tid < stride) s[tid] += s[tid + stride];
        __syncthreads();
    }
    if (tid == 0) out[0] = s[0];
}

// ---------------------------------------------------------------------------
// inputs (metadata order): emissions f32, tags i64-or-i32, mask i32,
//                          start_transitions f32, end_transitions f32,
//                          transitions f32.  output: f32 scalar.
// ---------------------------------------------------------------------------
extern "C" void kernel_launch(void* const* d_in, const int* in_sizes, int n_in,
                              void* d_out, int out_size)
{
    const float* em     = (const float*)d_in[0];
    const void*  tags   = d_in[1];
    const int*   mask   = (const int*)d_in[2];
    const float* startT = (const float*)d_in[3];
    const float* endT   = (const float*)d_in[4];
    const float* trans  = (const float*)d_in[5];
    float*       out    = (float*)d_out;

    detect_kernel<<<1, 1>>>((const int*)tags);
    numer_kernel<<<BATCH, 64>>>(em, tags, mask, startT, endT, trans);
    forward_kernel<<<BATCH, 64>>>(em, mask, startT, endT, trans);
    reduce_kernel<<<1, BATCH>>>(out);
}

// round 3
// speedup vs baseline: 2.5356x; 2.5356x over previous
#include <cuda_runtime.h>

#define SEQ    1024
#define BATCH  512
#define NT     64
#define CH     16
#define NCHUNK (SEQ / CH)

__device__ float g_num[BATCH];
__device__ float g_den[BATCH];
__device__ int   g_tags_is64;

// ---------------------------------------------------------------------------
// Detect tags dtype: int64 (odd int32 words all zero for values in [0,64))
// vs int32. 32 parallel loads + ballot.
// ---------------------------------------------------------------------------
__global__ void detect_kernel(const int* __restrict__ tags32)
{
    int x = tags32[2 * threadIdx.x + 1];
    unsigned nz = __ballot_sync(0xffffffffu, x != 0);
    if (threadIdx.x == 0) g_tags_is64 = (nz == 0) ? 1 : 0;
}

// ---------------------------------------------------------------------------
// Numerator: per-batch gold-path score
// ---------------------------------------------------------------------------
__global__ __launch_bounds__(64) void numer_kernel(
    const float* __restrict__ em,
    const void* __restrict__ tags_raw,
    const int* __restrict__ mask,
    const float* __restrict__ startT,
    const float* __restrict__ endT,
    const float* __restrict__ trans)
{
    int b   = blockIdx.x;
    int tid = threadIdx.x;  // 0..63

    const int is64 = g_tags_is64;
    const long long* tags64 = (const long long*)tags_raw;
    const int*       tags32 = (const int*)tags_raw;

    __shared__ int stags[SEQ];
    __shared__ int smask[SEQ];
    for (int t = tid; t < SEQ; t += 64) {
        size_t idx = (size_t)t * BATCH + b;
        stags[t] = is64 ? (int)tags64[idx] : tags32[idx];
        smask[t] = mask[t * BATCH + b];
    }
    __syncthreads();

    float score  = 0.f;
    int   mcount = 0;
    for (int t = tid; t < SEQ; t += 64) {
        int tg = stags[t];
        mcount += smask[t];
        if (t == 0) {
            score += startT[tg] + em[(size_t)b * NT + tg];
        } else if (smask[t]) {
            score += trans[stags[t - 1] * NT + tg] +
                     em[((size_t)t * BATCH + b) * NT + tg];
        }
    }

    #pragma unroll
    for (int o = 16; o; o >>= 1) {
        score  += __shfl_down_sync(0xffffffffu, score, o);
        mcount += __shfl_down_sync(0xffffffffu, mcount, o);
    }
    __shared__ float ws[2];
    __shared__ int   wm[2];
    if ((tid & 31) == 0) { ws[tid >> 5] = score; wm[tid >> 5] = mcount; }
    __syncthreads();
    if (tid == 0) {
        float s  = ws[0] + ws[1];
        int   mc = wm[0] + wm[1];
        s += endT[stags[mc - 1]];
        g_num[b] = s;
    }
}

// ---------------------------------------------------------------------------
// Normalizer: scaled forward algorithm in exp domain.
// One block per batch, 64 threads (thread j owns tag column j).
// E[:,j] = exp(T[:,j]) in registers. exp(em) staged through double-buffered
// smem, 16 steps per chunk, loads issued a full chunk ahead.
// Renorm every 8 steps by redundant block-wide sum of the freshly written
// alpha buffer (no shuffles, no extra sync); 1/s folded into next step.
// ---------------------------------------------------------------------------
__global__ __launch_bounds__(64) void forward_kernel(
    const float* __restrict__ em,
    const int* __restrict__ mask,
    const float* __restrict__ startT,
    const float* __restrict__ endT,
    const float* __restrict__ trans)
{
    const int b = blockIdx.x;
    const int j = threadIdx.x;  // 0..63

    float Ecol[NT];
    #pragma unroll
    for (int i = 0; i < NT; i++)
        Ecol[i] = __expf(trans[i * NT + j]);

    __shared__ __align__(16) float a_s[2][NT];
    __shared__ __align__(16) float eem[2][CH][NT];
    __shared__ int smask[SEQ];

    // preload mask column
    #pragma unroll
    for (int t0 = 0; t0 < SEQ; t0 += NT)
        smask[t0 + j] = mask[(t0 + j) * BATCH + b];

    // stage chunk 0 (t = 0..15)
    {
        float ld[CH];
        #pragma unroll
        for (int c = 0; c < CH; c++)
            ld[c] = em[((size_t)c * BATCH + b) * NT + j];
        #pragma unroll
        for (int c = 0; c < CH; c++)
            eem[0][c][j] = __expf(ld[c]);
    }

    // alpha0 = exp(start_j) * exp(em0_j)   (own smem write, safe to read)
    float a_prev = __expf(startT[j]) * eem[0][0][j];
    a_s[0][j] = a_prev;
    __syncthreads();

    float logacc = 0.f;
    float rs     = 1.0f;  // pending 1/s from last renorm (1 otherwise)
    int   p      = 0;

    for (int k = 0; k < NCHUNK; k++) {
        const int buf = k & 1;

        // issue global loads for chunk k+1 (a full chunk of latency cover)
        float ld[CH];
        if (k + 1 < NCHUNK) {
            const size_t base = ((size_t)(k + 1) * CH * BATCH + b) * NT + j;
            #pragma unroll
            for (int c = 0; c < CH; c++)
                ld[c] = em[base + (size_t)c * BATCH * NT];
        }

        const int c0 = (k == 0) ? 1 : 0;
        #pragma unroll 8
        for (int c = c0; c < CH; c++) {
            const int t  = k * CH + c;
            const int mc = smask[t];

            float acc0 = 0.f, acc1 = 0.f, acc2 = 0.f, acc3 = 0.f;
            #pragma unroll
            for (int i = 0; i < NT; i += 4) {
                float4 av = *(const float4*)&a_s[p][i];  // broadcast
                acc0 = fmaf(av.x, Ecol[i + 0], acc0);
                acc1 = fmaf(av.y, Ecol[i + 1], acc1);
                acc2 = fmaf(av.z, Ecol[i + 2], acc2);
                acc3 = fmaf(av.w, Ecol[i + 3], acc3);
            }
            float dot = (acc0 + acc1) + (acc2 + acc3);
            float v   = mc ? dot * (eem[buf][c][j] * rs) : a_prev * rs;

            a_s[p ^ 1][j] = v;
            a_prev = v;
            __syncthreads();
            p ^= 1;

            if ((t & 7) == 0) {   // compile-time under unroll (c & 7 == 0)
                float s = 0.f;
                #pragma unroll
                for (int i = 0; i < NT; i += 4) {
                    float4 w = *(const float4*)&a_s[p][i];
                    s += (w.x + w.y) + (w.z + w.w);
                }
                rs = __fdividef(1.0f, s);
                logacc += __logf(s);
            } else {
                rs = 1.0f;
            }
        }

        // finish staging chunk k+1 (loads returned during the 16 steps)
        if (k + 1 < NCHUNK) {
            #pragma unroll
            for (int c = 0; c < CH; c++)
                eem[buf ^ 1][c][j] = __expf(ld[c]);
        }
        __syncthreads();
    }

    // logZ = logacc + log( sum_j alpha_j * exp(end_j) )   (rs is 1 here:
    // last renorm at t=1016 was consumed at t=1017)
    float ve = a_s[p][j] * __expf(endT[j]);
    a_s[p ^ 1][j] = ve;
    __syncthreads();
    if (j == 0) {
        float s = 0.f;
        #pragma unroll
        for (int i = 0; i < NT; i += 4) {
            float4 w = *(const float4*)&a_s[p ^ 1][i];
            s += (w.x + w.y) + (w.z + w.w);
        }
        g_den[b] = logacc + __logf(s);
    }
}

// ---------------------------------------------------------------------------
// Deterministic final reduction: out = sum_b (num[b] - den[b])
// ---------------------------------------------------------------------------
__global__ __launch_bounds__(512) void reduce_kernel(float* __restrict__ out)
{
    int tid = threadIdx.x;  // 0..511
    float v = g_num[tid] - g_den[tid];
    #pragma unroll
    for (int o = 16; o; o >>= 1)
        v += __shfl_down_sync(0xffffffffu, v, o);
    __shared__ float ws[16];
    if ((tid & 31) == 0) ws[tid >> 5] = v;
    __syncthreads();
    if (tid < 32) {
        v = (tid < 16) ? ws[tid] : 0.f;
        #pragma unroll
        for (int o = 8; o; o >>= 1)
            v += __shfl_down_sync(0xffffffffu, v, o);
        if (tid == 0) out[0] = v;
    }
}

// ---------------------------------------------------------------------------
// inputs (metadata order): emissions f32, tags i64-or-i32, mask i32,
//                          start_transitions f32, end_transitions f32,
//                          transitions f32.  output: f32 scalar.
// ---------------------------------------------------------------------------
extern "C" void kernel_launch(void* const* d_in, const int* in_sizes, int n_in,
                              void* d_out, int out_size)
{
    const float* em     = (const float*)d_in[0];
    const void*  tags   = d_in[1];
    const int*   mask   = (const int*)d_in[2];
    const float* startT = (const float*)d_in[3];
    const float* endT   = (const float*)d_in[4];
    const float* trans  = (const float*)d_in[5];
    float*       out    = (float*)d_out;

    detect_kernel<<<1, 32>>>((const int*)tags);
    numer_kernel<<<BATCH, 64>>>(em, tags, mask, startT, endT, trans);
    forward_kernel<<<BATCH, 64>>>(em, mask, startT, endT, trans);
    reduce_kernel<<<1, 512>>>(out);
}

// round 4
// speedup vs baseline: 2.9001x; 1.1438x over previous
#include <cuda_runtime.h>

typedef unsigned long long u64;

#define SEQ    1024
#define BATCH  512
#define NT     64
#define CH     16
#define NCHUNK (SEQ / CH)

__device__ float g_num[BATCH];
__device__ float g_den[BATCH];
__device__ int   g_tags_is64;

// ---- packed f32x2 helpers (FFMA2 path, sm_100+) ----
__device__ __forceinline__ u64 fma2(u64 a, u64 b, u64 c) {
    u64 d; asm("fma.rn.f32x2 %0, %1, %2, %3;" : "=l"(d) : "l"(a), "l"(b), "l"(c));
    return d;
}
__device__ __forceinline__ u64 add2(u64 a, u64 b) {
    u64 d; asm("add.rn.f32x2 %0, %1, %2;" : "=l"(d) : "l"(a), "l"(b));
    return d;
}
__device__ __forceinline__ float2 unpack2(u64 a) {
    float2 r; asm("mov.b64 {%0,%1}, %2;" : "=f"(r.x), "=f"(r.y) : "l"(a));
    return r;
}
__device__ __forceinline__ u64 pack2(float x, float y) {
    u64 d; asm("mov.b64 %0, {%1,%2};" : "=l"(d) : "f"(x), "f"(y));
    return d;
}

// ---------------------------------------------------------------------------
// Detect tags dtype: int64 (odd int32 words all zero for values in [0,64))
// vs int32. 32 parallel loads + ballot.
// ---------------------------------------------------------------------------
__global__ void detect_kernel(const int* __restrict__ tags32)
{
    int x = tags32[2 * threadIdx.x + 1];
    unsigned nz = __ballot_sync(0xffffffffu, x != 0);
    if (threadIdx.x == 0) g_tags_is64 = (nz == 0) ? 1 : 0;
}

// ---------------------------------------------------------------------------
// Fused kernel: scaled forward algorithm (exp domain) + gold-path numerator.
// One block per batch, 64 threads; thread j owns tag column j.
// E packed as f32x2 pairs in registers; emissions staged via double-buffered
// smem exp(em), one chunk (16 steps) of latency lead. Numerator gathers are
// issued at chunk top k and consumed at chunk top k+1 (fully latency-hidden).
// ---------------------------------------------------------------------------
__global__ __launch_bounds__(64) void fused_kernel(
    const float* __restrict__ em,
    const void* __restrict__ tags_raw,
    const int* __restrict__ mask,
    const float* __restrict__ startT,
    const float* __restrict__ endT,
    const float* __restrict__ trans)
{
    const int b = blockIdx.x;
    const int j = threadIdx.x;  // 0..63

    const int is64 = g_tags_is64;
    const long long* tags64 = (const long long*)tags_raw;
    const int*       tags32 = (const int*)tags_raw;

    // E2[q] = ( exp(T[2q][j]), exp(T[2q+1][j]) )
    u64 E2[NT / 2];
    #pragma unroll
    for (int q = 0; q < NT / 2; q++)
        E2[q] = pack2(__expf(trans[(2 * q) * NT + j]),
                      __expf(trans[(2 * q + 1) * NT + j]));

    __shared__ __align__(16) float a_s[2][NT];
    __shared__ __align__(16) float eem[2][CH][NT];
    __shared__ int stags[SEQ];
    __shared__ int smask[SEQ];

    // preload tags + mask columns; accumulate mask count
    int mcnt = 0;
    #pragma unroll
    for (int t0 = 0; t0 < SEQ; t0 += NT) {
        int t  = t0 + j;
        int mv = mask[t * BATCH + b];
        smask[t] = mv;
        mcnt += mv;
        size_t idx = (size_t)t * BATCH + b;
        stags[t] = is64 ? (int)tags64[idx] : tags32[idx];
    }

    // stage chunk 0 (t = 0..15)
    {
        float ld[CH];
        #pragma unroll
        for (int c = 0; c < CH; c++)
            ld[c] = em[((size_t)c * BATCH + b) * NT + j];
        #pragma unroll
        for (int c = 0; c < CH; c++)
            eem[0][c][j] = __expf(ld[c]);
    }

    float a_prev = __expf(startT[j]) * eem[0][0][j];
    a_s[0][j] = a_prev;
    __syncthreads();

    float logacc = 0.f;
    float rs     = 1.0f;
    int   p      = 0;

    // numerator pipeline state
    float score = 0.f;
    float tv_p = 0.f, ev_p = 0.f;
    int   pm_p = 0;

    for (int k = 0; k < NCHUNK; k++) {
        const int buf = k & 1;

        // issue emission loads for chunk k+1
        float ldn[CH];
        if (k + 1 < NCHUNK) {
            const size_t base = ((size_t)(k + 1) * CH * BATCH + b) * NT + j;
            #pragma unroll
            for (int c = 0; c < CH; c++)
                ldn[c] = em[base + (size_t)c * BATCH * NT];
        }

        // numer: consume gathers issued last chunk
        if (k >= 1 && k <= 16)
            score += pm_p ? (tv_p + ev_p) : 0.f;

        // numer: issue gathers for this chunk's slice (k < 16)
        if (k < 16) {
            int t   = k * NT + j;
            int cur = stags[t];
            if (t == 0) {
                tv_p = startT[cur];
                ev_p = em[(size_t)b * NT + cur];
                pm_p = 1;
            } else {
                pm_p = smask[t];
                tv_p = trans[stags[t - 1] * NT + cur];
                ev_p = em[((size_t)t * BATCH + b) * NT + cur];
            }
        }

        const int c0 = (k == 0) ? 1 : 0;
        #pragma unroll 8
        for (int c = c0; c < CH; c++) {
            const int t  = k * CH + c;
            const int mc = smask[t];

            const ulonglong2* ap = (const ulonglong2*)a_s[p];
            u64 acc0 = 0ull, acc1 = 0ull, acc2 = 0ull, acc3 = 0ull;
            #pragma unroll
            for (int q = 0; q < 16; q += 2) {
                ulonglong2 v0 = ap[q];
                ulonglong2 v1 = ap[q + 1];
                acc0 = fma2(v0.x, E2[2 * q + 0], acc0);
                acc1 = fma2(v0.y, E2[2 * q + 1], acc1);
                acc2 = fma2(v1.x, E2[2 * q + 2], acc2);
                acc3 = fma2(v1.y, E2[2 * q + 3], acc3);
            }
            float2 sp = unpack2(add2(add2(acc0, acc1), add2(acc2, acc3)));
            float dot = sp.x + sp.y;
            float v   = mc ? dot * (eem[buf][c][j] * rs) : a_prev * rs;

            a_s[p ^ 1][j] = v;
            a_prev = v;
            __syncthreads();
            p ^= 1;

            if ((t & 7) == 0) {  // compile-time under unroll
                const ulonglong2* wp = (const ulonglong2*)a_s[p];
                u64 s0 = 0ull, s1 = 0ull;
                #pragma unroll
                for (int q = 0; q < 16; q += 2) {
                    ulonglong2 w0 = wp[q];
                    ulonglong2 w1 = wp[q + 1];
                    s0 = add2(s0, add2(w0.x, w0.y));
                    s1 = add2(s1, add2(w1.x, w1.y));
                }
                float2 f = unpack2(add2(s0, s1));
                float s  = f.x + f.y;
                rs = __fdividef(1.0f, s);
                logacc += __logf(s);
            } else {
                rs = 1.0f;
            }
        }

        // finish staging chunk k+1
        if (k + 1 < NCHUNK) {
            #pragma unroll
            for (int c = 0; c < CH; c++)
                eem[buf ^ 1][c][j] = __expf(ldn[c]);
        }
        __syncthreads();
    }

    // ---- denominator epilogue ----
    float ve = a_s[p][j] * __expf(endT[j]);
    a_s[p ^ 1][j] = ve;
    __syncthreads();
    if (j == 0) {
        float s = 0.f;
        #pragma unroll
        for (int i = 0; i < NT; i += 4) {
            float4 w = *(const float4*)&a_s[p ^ 1][i];
            s += (w.x + w.y) + (w.z + w.w);
        }
        g_den[b] = logacc + __logf(s);
    }

    // ---- numerator epilogue ----
    #pragma unroll
    for (int o = 16; o; o >>= 1) {
        score += __shfl_down_sync(0xffffffffu, score, o);
        mcnt  += __shfl_down_sync(0xffffffffu, mcnt, o);
    }
    __shared__ float ws[2];
    __shared__ int   wm[2];
    if ((j & 31) == 0) { ws[j >> 5] = score; wm[j >> 5] = mcnt; }
    __syncthreads();
    if (j == 0) {
        float s  = ws[0] + ws[1];
        int   tc = wm[0] + wm[1];
        s += endT[stags[tc - 1]];
        g_num[b] = s;
    }
}

// ---------------------------------------------------------------------------
// Deterministic final reduction: out = sum_b (num[b] - den[b])
// ---------------------------------------------------------------------------
__global__ __launch_bounds__(512) void reduce_kernel(float* __restrict__ out)
{
    int tid = threadIdx.x;
    float v = g_num[tid] - g_den[tid];
    #pragma unroll
    for (int o = 16; o; o >>= 1)
        v += __shfl_down_sync(0xffffffffu, v, o);
    __shared__ float ws[16];
    if ((tid & 31) == 0) ws[tid >> 5] = v;
    __syncthreads();
    if (tid < 32) {
        v = (tid < 16) ? ws[tid] : 0.f;
        #pragma unroll
        for (int o = 8; o; o >>= 1)
            v += __shfl_down_sync(0xffffffffu, v, o);
        if (tid == 0) out[0] = v;
    }
}

// ---------------------------------------------------------------------------
// inputs (metadata order): emissions f32, tags i64-or-i32, mask i32,
//                          start_transitions f32, end_transitions f32,
//                          transitions f32.  output: f32 scalar.
// ---------------------------------------------------------------------------
extern "C" void kernel_launch(void* const* d_in, const int* in_sizes, int n_in,
                              void* d_out, int out_size)
{
    const float* em     = (const float*)d_in[0];
    const void*  tags   = d_in[1];
    const int*   mask   = (const int*)d_in[2];
    const float* startT = (const float*)d_in[3];
    const float* endT   = (const float*)d_in[4];
    const float* trans  = (const float*)d_in[5];
    float*       out    = (float*)d_out;

    detect_kernel<<<1, 32>>>((const int*)tags);
    fused_kernel<<<BATCH, 64>>>(em, tags, mask, startT, endT, trans);
    reduce_kernel<<<1, 512>>>(out);
}

// round 5
// speedup vs baseline: 3.9653x; 1.3673x over previous
#include <cuda_runtime.h>

typedef unsigned long long u64;

#define SEQ    1024
#define BATCH  512
#define NT     64
#define CH     8
#define NCHUNK (SEQ / CH)   /* 128 */
#define WPB    4            /* warps (=batches) per block */
#define NBLK   (BATCH / WPB)

__device__ float g_num[BATCH];
__device__ float g_den[BATCH];

// ---- packed f32x2 helpers ----
__device__ __forceinline__ u64 fma2(u64 a, u64 b, u64 c) {
    u64 d; asm("fma.rn.f32x2 %0, %1, %2, %3;" : "=l"(d) : "l"(a), "l"(b), "l"(c));
    return d;
}
__device__ __forceinline__ u64 add2(u64 a, u64 b) {
    u64 d; asm("add.rn.f32x2 %0, %1, %2;" : "=l"(d) : "l"(a), "l"(b));
    return d;
}
__device__ __forceinline__ float2 unpack2(u64 a) {
    float2 r; asm("mov.b64 {%0,%1}, %2;" : "=f"(r.x), "=f"(r.y) : "l"(a));
    return r;
}
__device__ __forceinline__ u64 pack2(float x, float y) {
    u64 d; asm("mov.b64 %0, {%1,%2};" : "=l"(d) : "f"(x), "f"(y));
    return d;
}

// ---------------------------------------------------------------------------
// Fused kernel: one WARP per batch (no cross-warp syncs). Lane j owns output
// columns j and j+32. Scaled forward algorithm in exp domain + fused gold-path
// numerator, emissions staged chunk-ahead through per-warp smem.
// ---------------------------------------------------------------------------
__global__ __launch_bounds__(128, 1) void fused_kernel(
    const float* __restrict__ em,
    const void* __restrict__ tags_raw,
    const int* __restrict__ mask,
    const float* __restrict__ startT,
    const float* __restrict__ endT,
    const float* __restrict__ trans)
{
    const int w = threadIdx.x >> 5;   // warp in block: 0..3
    const int j = threadIdx.x & 31;   // lane
    const int b = blockIdx.x * WPB + w;

    // ---- tags dtype detect (int64 written by x64-jax vs int32 default) ----
    const int*       tags32 = (const int*)tags_raw;
    const long long* tags64 = (const long long*)tags_raw;
    unsigned nz = __ballot_sync(0xffffffffu, tags32[2 * j + 1] != 0);
    const int is64 = (nz == 0);

    // ---- E pairs in registers: E2a/E2b[r] = (expT[2r][c], expT[2r+1][c]) ----
    u64 E2a[NT / 2], E2b[NT / 2];
    #pragma unroll
    for (int r = 0; r < NT / 2; r++) {
        E2a[r] = pack2(__expf(trans[(2 * r) * NT + j]),
                       __expf(trans[(2 * r + 1) * NT + j]));
        E2b[r] = pack2(__expf(trans[(2 * r) * NT + j + 32]),
                       __expf(trans[(2 * r + 1) * NT + j + 32]));
    }

    __shared__ __align__(16) float a_s[WPB][2][NT];
    __shared__ __align__(16) float eem[WPB][2][CH][NT];
    __shared__ short stags[WPB][SEQ];
    __shared__ char  smask[WPB][SEQ];

    // ---- preload tags + mask columns for this batch ----
    int mcnt = 0;
    #pragma unroll
    for (int t0 = 0; t0 < SEQ; t0 += 32) {
        int t = t0 + j;
        int mv = mask[t * BATCH + b];
        smask[w][t] = (char)mv;
        mcnt += mv;
        size_t idx = (size_t)t * BATCH + b;
        stags[w][t] = (short)(is64 ? (int)tags64[idx] : tags32[idx]);
    }

    // ---- stage chunk 0 ----
    {
        float l0[CH], l1[CH];
        #pragma unroll
        for (int c = 0; c < CH; c++) {
            size_t base = ((size_t)c * BATCH + b) * NT;
            l0[c] = em[base + j];
            l1[c] = em[base + j + 32];
        }
        #pragma unroll
        for (int c = 0; c < CH; c++) {
            eem[w][0][c][j]      = __expf(l0[c]);
            eem[w][0][c][j + 32] = __expf(l1[c]);
        }
    }
    __syncwarp();

    // alpha0
    float a_pa = __expf(startT[j])      * eem[w][0][0][j];
    float a_pb = __expf(startT[j + 32]) * eem[w][0][0][j + 32];
    a_s[w][0][j]      = a_pa;
    a_s[w][0][j + 32] = a_pb;
    __syncwarp();

    float logacc = 0.f;
    float rs     = 1.0f;
    int   p      = 0;

    // numerator pipeline state (slice t = k*32 + j, k < 32)
    float score = 0.f;
    float tv_p = 0.f, ev_p = 0.f;
    int   pm_p = 0;

    for (int k = 0; k < NCHUNK; k++) {
        const int buf = k & 1;

        // issue emission loads for chunk k+1
        float l0[CH], l1[CH];
        if (k + 1 < NCHUNK) {
            const size_t base = ((size_t)(k + 1) * CH * BATCH + b) * NT;
            #pragma unroll
            for (int c = 0; c < CH; c++) {
                size_t o = base + (size_t)c * BATCH * NT;
                l0[c] = em[o + j];
                l1[c] = em[o + j + 32];
            }
        }

        // numerator: consume last chunk's gathers, issue this chunk's
        if (k >= 1 && k <= 32)
            score += pm_p ? (tv_p + ev_p) : 0.f;
        if (k < 32) {
            int t   = k * 32 + j;
            int cur = stags[w][t];
            if (t == 0) {
                tv_p = startT[cur];
                ev_p = em[(size_t)b * NT + cur];
                pm_p = 1;
            } else {
                pm_p = smask[w][t];
                tv_p = trans[stags[w][t - 1] * NT + cur];
                ev_p = em[((size_t)t * BATCH + b) * NT + cur];
            }
        }

        const int c0 = (k == 0) ? 1 : 0;
        #pragma unroll
        for (int c = 0; c < CH; c++) {
            if (c < c0) continue;

            // renorm result from step t-1 (t-1 % 8 == 7)? No: renorm lives
            // below; rs was set after previous step when (t-1)&7==0.
            const int t  = k * CH + c;
            const int mc = smask[w][t];

            const ulonglong2* ap = (const ulonglong2*)a_s[w][p];
            u64 aA[4] = {0ull, 0ull, 0ull, 0ull};
            u64 aB[4] = {0ull, 0ull, 0ull, 0ull};
            #pragma unroll
            for (int q = 0; q < 16; q++) {          // 16 x LDS.128 broadcast
                ulonglong2 v = ap[q];
                const int r = 2 * q;
                aA[r & 3]       = fma2(v.x, E2a[r],     aA[r & 3]);
                aA[(r + 1) & 3] = fma2(v.y, E2a[r + 1], aA[(r + 1) & 3]);
                aB[r & 3]       = fma2(v.x, E2b[r],     aB[r & 3]);
                aB[(r + 1) & 3] = fma2(v.y, E2b[r + 1], aB[(r + 1) & 3]);
            }
            float2 fA = unpack2(add2(add2(aA[0], aA[1]), add2(aA[2], aA[3])));
            float2 fB = unpack2(add2(add2(aB[0], aB[1]), add2(aB[2], aB[3])));
            float dotA = fA.x + fA.y;
            float dotB = fB.x + fB.y;

            float v_a = mc ? dotA * (eem[w][buf][c][j] * rs)      : a_pa * rs;
            float v_b = mc ? dotB * (eem[w][buf][c][j + 32] * rs) : a_pb * rs;

            a_s[w][p ^ 1][j]      = v_a;
            a_s[w][p ^ 1][j + 32] = v_b;
            a_pa = v_a;
            a_pb = v_b;
            __syncwarp();
            p ^= 1;

            if (c == 0) {   // t % 8 == 0 (k>=1 only; k==0 starts at c=1)
                const ulonglong2* wp2 = (const ulonglong2*)a_s[w][p];
                u64 s0 = 0ull, s1 = 0ull;
                #pragma unroll
                for (int q = 0; q < 16; q += 2) {
                    ulonglong2 w0 = wp2[q];
                    ulonglong2 w1 = wp2[q + 1];
                    s0 = add2(s0, add2(w0.x, w0.y));
                    s1 = add2(s1, add2(w1.x, w1.y));
                }
                float2 f = unpack2(add2(s0, s1));
                float s  = f.x + f.y;
                rs = __fdividef(1.0f, s);      // consumed next step
                logacc += __logf(s);
            } else {
                rs = 1.0f;
            }
        }

        // finish staging chunk k+1
        if (k + 1 < NCHUNK) {
            #pragma unroll
            for (int c = 0; c < CH; c++) {
                eem[w][buf ^ 1][c][j]      = __expf(l0[c]);
                eem[w][buf ^ 1][c][j + 32] = __expf(l1[c]);
            }
        }
        __syncwarp();
    }

    // ---- denominator epilogue (warp-local) ----
    float s = a_pa * __expf(endT[j]) + a_pb * __expf(endT[j + 32]);
    #pragma unroll
    for (int o = 16; o; o >>= 1)
        s += __shfl_xor_sync(0xffffffffu, s, o);
    if (j == 0)
        g_den[b] = logacc + __logf(s);

    // ---- numerator epilogue (warp-local) ----
    #pragma unroll
    for (int o = 16; o; o >>= 1) {
        score += __shfl_down_sync(0xffffffffu, score, o);
        mcnt  += __shfl_down_sync(0xffffffffu, mcnt, o);
    }
    if (j == 0)
        g_num[b] = score + endT[stags[w][mcnt - 1]];
}

// ---------------------------------------------------------------------------
// Deterministic final reduction: out = sum_b (num[b] - den[b])
// ---------------------------------------------------------------------------
__global__ __launch_bounds__(512) void reduce_kernel(float* __restrict__ out)
{
    int tid = threadIdx.x;
    float v = g_num[tid] - g_den[tid];
    #pragma unroll
    for (int o = 16; o; o >>= 1)
        v += __shfl_down_sync(0xffffffffu, v, o);
    __shared__ float ws[16];
    if ((tid & 31) == 0) ws[tid >> 5] = v;
    __syncthreads();
    if (tid < 32) {
        v = (tid < 16) ? ws[tid] : 0.f;
        #pragma unroll
        for (int o = 8; o; o >>= 1)
            v += __shfl_down_sync(0xffffffffu, v, o);
        if (tid == 0) out[0] = v;
    }
}

// ---------------------------------------------------------------------------
// inputs (metadata order): emissions f32, tags i64-or-i32, mask i32,
//                          start_transitions f32, end_transitions f32,
//                          transitions f32.  output: f32 scalar.
// ---------------------------------------------------------------------------
extern "C" void kernel_launch(void* const* d_in, const int* in_sizes, int n_in,
                              void* d_out, int out_size)
{
    const float* em     = (const float*)d_in[0];
    const void*  tags   = d_in[1];
    const int*   mask   = (const int*)d_in[2];
    const float* startT = (const float*)d_in[3];
    const float* endT   = (const float*)d_in[4];
    const float* trans  = (const float*)d_in[5];
    float*       out    = (float*)d_out;

    fused_kernel<<<NBLK, 32 * WPB>>>(em, tags, mask, startT, endT, trans);
    reduce_kernel<<<1, 512>>>(out);
}

// round 6
// speedup vs baseline: 3.9991x; 1.0085x over previous
#include <cuda_runtime.h>

typedef unsigned long long u64;

#define SEQ    1024
#define BATCH  512
#define NT     64
#define CH     8
#define NCHUNK (SEQ / CH)   /* 128 */
#define WPB    4            /* warps (=batches) per block */
#define NBLK   (BATCH / WPB)

__device__ float    g_num[BATCH];
__device__ float    g_den[BATCH];
__device__ unsigned g_cnt;   /* zero-initialized; self-resets each launch */

// ---- packed f32x2 helpers ----
__device__ __forceinline__ u64 fma2(u64 a, u64 b, u64 c) {
    u64 d; asm("fma.rn.f32x2 %0, %1, %2, %3;" : "=l"(d) : "l"(a), "l"(b), "l"(c));
    return d;
}
__device__ __forceinline__ u64 add2(u64 a, u64 b) {
    u64 d; asm("add.rn.f32x2 %0, %1, %2;" : "=l"(d) : "l"(a), "l"(b));
    return d;
}
__device__ __forceinline__ float2 unpack2(u64 a) {
    float2 r; asm("mov.b64 {%0,%1}, %2;" : "=f"(r.x), "=f"(r.y) : "l"(a));
    return r;
}
__device__ __forceinline__ u64 pack2(float x, float y) {
    u64 d; asm("mov.b64 %0, {%1,%2};" : "=l"(d) : "f"(x), "f"(y));
    return d;
}

// ---------------------------------------------------------------------------
// Fused kernel: one WARP per batch. Lane j owns columns j and j+32.
// Alpha buffer interleaved: slot 2j = col j, slot 2j+1 = col j+32 (STS.64
// writeback). Emissions staged per-lane in registers (no smem). Scaled
// forward algorithm in exp domain + fused gold-path numerator + last-block
// final reduction.
// ---------------------------------------------------------------------------
__global__ __launch_bounds__(128, 1) void fused_kernel(
    const float* __restrict__ em,
    const void* __restrict__ tags_raw,
    const int* __restrict__ mask,
    const float* __restrict__ startT,
    const float* __restrict__ endT,
    const float* __restrict__ trans,
    float* __restrict__ out)
{
    const int w = threadIdx.x >> 5;   // warp in block: 0..3
    const int j = threadIdx.x & 31;   // lane
    const int b = blockIdx.x * WPB + w;

    // ---- tags dtype detect (jax x64 -> int64, default -> int32) ----
    const int*       tags32 = (const int*)tags_raw;
    const long long* tags64 = (const long long*)tags_raw;
    unsigned nz = __ballot_sync(0xffffffffu, tags32[2 * j + 1] != 0);
    const int is64 = (nz == 0);

    // ---- E pairs matching interleaved alpha slots:
    //      slot pair i holds alpha rows (i, i+32)
    u64 EPa[32], EPb[32];
    #pragma unroll
    for (int i = 0; i < 32; i++) {
        EPa[i] = pack2(__expf(trans[i * NT + j]),
                       __expf(trans[(i + 32) * NT + j]));
        EPb[i] = pack2(__expf(trans[i * NT + j + 32]),
                       __expf(trans[(i + 32) * NT + j + 32]));
    }

    __shared__ __align__(16) float a_s[WPB][2][NT];
    __shared__ short stags[WPB][SEQ];
    __shared__ __align__(8) char smask[WPB][SEQ];

    // ---- preload tags + mask columns ----
    int mcnt = 0;
    #pragma unroll
    for (int t0 = 0; t0 < SEQ; t0 += 32) {
        int t  = t0 + j;
        int mv = mask[t * BATCH + b];
        smask[w][t] = (char)mv;
        mcnt += mv;
        size_t idx = (size_t)t * BATCH + b;
        stags[w][t] = (short)(is64 ? (int)tags64[idx] : tags32[idx]);
    }

    // ---- stage chunk 0 emissions into registers ----
    float eca[CH], ecb[CH];
    #pragma unroll
    for (int c = 0; c < CH; c++) {
        size_t base = ((size_t)c * BATCH + b) * NT;
        eca[c] = em[base + j];
        ecb[c] = em[base + j + 32];
    }
    #pragma unroll
    for (int c = 0; c < CH; c++) {
        eca[c] = __expf(eca[c]);
        ecb[c] = __expf(ecb[c]);
    }

    // alpha0 (interleaved write: one float2)
    float a_pa = __expf(startT[j])      * eca[0];
    float a_pb = __expf(startT[j + 32]) * ecb[0];
    *(float2*)&a_s[w][0][2 * j] = make_float2(a_pa, a_pb);
    __syncwarp();

    float logacc = 0.f;
    float rs     = 1.0f;
    int   p      = 0;

    // numerator pipeline state (slice t = k*32 + j, valid for k < 32)
    float score = 0.f;
    float tv_p = 0.f, ev_p = 0.f;
    int   pm_p = 0;

    for (int k = 0; k < NCHUNK; k++) {
        // issue emission loads for chunk k+1 (register destination)
        float lda[CH], ldb[CH];
        if (k + 1 < NCHUNK) {
            const size_t base = ((size_t)(k + 1) * CH * BATCH + b) * NT;
            #pragma unroll
            for (int c = 0; c < CH; c++) {
                size_t o = base + (size_t)c * BATCH * NT;
                lda[c] = em[o + j];
                ldb[c] = em[o + j + 32];
            }
        }

        // mask bytes for this chunk: one LDS.64
        const u64 mword = *(const u64*)&smask[w][k * CH];

        // numerator: consume last chunk's gathers, issue this chunk's
        if (k >= 1 && k <= 32)
            score += pm_p ? (tv_p + ev_p) : 0.f;
        if (k < 32) {
            int t   = k * 32 + j;
            int cur = stags[w][t];
            if (t == 0) {
                tv_p = startT[cur];
                ev_p = em[(size_t)b * NT + cur];
                pm_p = 1;
            } else {
                pm_p = smask[w][t];
                tv_p = trans[stags[w][t - 1] * NT + cur];
                ev_p = em[((size_t)t * BATCH + b) * NT + cur];
            }
        }

        const int c0 = (k == 0) ? 1 : 0;
        #pragma unroll
        for (int c = 0; c < CH; c++) {
            if (c < c0) continue;

            const int mc = (int)((mword >> (8 * c)) & 0xff);

            const ulonglong2* ap = (const ulonglong2*)a_s[w][p];
            u64 aA[4] = {0ull, 0ull, 0ull, 0ull};
            u64 aB[4] = {0ull, 0ull, 0ull, 0ull};
            #pragma unroll
            for (int q = 0; q < 16; q++) {          // 16 x LDS.128 broadcast
                ulonglong2 v = ap[q];
                const int r = 2 * q;
                aA[r & 3]       = fma2(v.x, EPa[r],     aA[r & 3]);
                aA[(r + 1) & 3] = fma2(v.y, EPa[r + 1], aA[(r + 1) & 3]);
                aB[r & 3]       = fma2(v.x, EPb[r],     aB[r & 3]);
                aB[(r + 1) & 3] = fma2(v.y, EPb[r + 1], aB[(r + 1) & 3]);
            }
            float2 fA = unpack2(add2(add2(aA[0], aA[1]), add2(aA[2], aA[3])));
            float2 fB = unpack2(add2(add2(aB[0], aB[1]), add2(aB[2], aB[3])));
            float dotA = fA.x + fA.y;
            float dotB = fB.x + fB.y;

            float v_a = mc ? dotA * (eca[c] * rs) : a_pa * rs;
            float v_b = mc ? dotB * (ecb[c] * rs) : a_pb * rs;

            *(float2*)&a_s[w][p ^ 1][2 * j] = make_float2(v_a, v_b);
            a_pa = v_a;
            a_pb = v_b;
            __syncwarp();
            p ^= 1;

            if (c == 0) {   // t % 8 == 0 renorm (k>=1; k==0 starts at c=1)
                const ulonglong2* wp2 = (const ulonglong2*)a_s[w][p];
                u64 s0 = 0ull, s1 = 0ull;
                #pragma unroll
                for (int q = 0; q < 16; q += 2) {
                    ulonglong2 w0 = wp2[q];
                    ulonglong2 w1 = wp2[q + 1];
                    s0 = add2(s0, add2(w0.x, w0.y));
                    s1 = add2(s1, add2(w1.x, w1.y));
                }
                float2 f = unpack2(add2(s0, s1));
                float s  = f.x + f.y;
                rs = __fdividef(1.0f, s);      // consumed next step
                logacc += __logf(s);
            } else {
                rs = 1.0f;
            }
        }

        // exp the staged loads for chunk k+1 (registers; no sync needed)
        if (k + 1 < NCHUNK) {
            #pragma unroll
            for (int c = 0; c < CH; c++) {
                eca[c] = __expf(lda[c]);
                ecb[c] = __expf(ldb[c]);
            }
        }
    }

    // ---- denominator epilogue (warp-local) ----
    float s = a_pa * __expf(endT[j]) + a_pb * __expf(endT[j + 32]);
    #pragma unroll
    for (int o = 16; o; o >>= 1)
        s += __shfl_xor_sync(0xffffffffu, s, o);
    if (j == 0)
        g_den[b] = logacc + __logf(s);

    // ---- numerator epilogue (warp-local) ----
    #pragma unroll
    for (int o = 16; o; o >>= 1) {
        score += __shfl_down_sync(0xffffffffu, score, o);
        mcnt  += __shfl_down_sync(0xffffffffu, mcnt, o);
    }
    if (j == 0)
        g_num[b] = score + endT[stags[w][mcnt - 1]];

    // ---- last-block final reduction (deterministic: fixed sum order) ----
    __threadfence();
    __syncthreads();
    __shared__ int is_last;
    if (threadIdx.x == 0) {
        unsigned prev = atomicAdd(&g_cnt, 1u);
        is_last = (prev == NBLK - 1);
    }
    __syncthreads();
    if (is_last) {
        __threadfence();  // acquire: make other blocks' g_num/g_den visible
        int tid = threadIdx.x;  // 0..127
        float v = 0.f;
        #pragma unroll
        for (int r = 0; r < BATCH / 128; r++) {
            int i = tid + r * 128;
            v += g_num[i] - g_den[i];
        }
        #pragma unroll
        for (int o = 16; o; o >>= 1)
            v += __shfl_down_sync(0xffffffffu, v, o);
        __shared__ float ws[4];
        if ((tid & 31) == 0) ws[tid >> 5] = v;
        __syncthreads();
        if (tid == 0) {
            out[0] = (ws[0] + ws[1]) + (ws[2] + ws[3]);
            g_cnt = 0;   // reset for next graph replay
        }
    }
}

// ---------------------------------------------------------------------------
// inputs (metadata order): emissions f32, tags i64-or-i32, mask i32,
//                          start_transitions f32, end_transitions f32,
//                          transitions f32.  output: f32 scalar.
// ---------------------------------------------------------------------------
extern "C" void kernel_launch(void* const* d_in, const int* in_sizes, int n_in,
                              void* d_out, int out_size)
{
    const float* em     = (const float*)d_in[0];
    const void*  tags   = d_in[1];
    const int*   mask   = (const int*)d_in[2];
    const float* startT = (const float*)d_in[3];
    const float* endT   = (const float*)d_in[4];
    const float* trans  = (const float*)d_in[5];
    float*       out    = (float*)d_out;

    fused_kernel<<<NBLK, 32 * WPB>>>(em, tags, mask, startT, endT, trans, out);
}